// round 15
// baseline (speedup 1.0000x reference)
#include <cuda_runtime.h>
#include <cuda_bf16.h>
#include <math.h>
#include <stdint.h>

// Problem constants
#define Bc 2
#define Tc 2048
#define Dc 1024
#define Hc 16
#define Lc 8
#define Ic 4096
#define HD 64
#define ROWS (Bc*Tc)    // 4096 token rows
#define LN_EPS 1e-5f
#define MASK_BIAS -10000.0f

typedef __nv_bfloat16 bf16;

// ---------------- scratch (static device globals; no allocation) -------------
__device__ float g_h[ROWS * Dc];            // residual stream (fp32)
__device__ bf16  g_qhi[ROWS * 3 * Dc], g_qlo[ROWS * 3 * Dc];  // qkv split
__device__ bf16  g_xhi[ROWS * Dc],  g_xlo[ROWS * Dc];     // LN output split
__device__ bf16  g_chi[ROWS * Dc],  g_clo[ROWS * Dc];     // attention ctx split
__device__ bf16  g_ahi[ROWS * Ic],  g_alo[ROWS * Ic];     // ffn inner split
// weight splits [K, N] layout
__device__ bf16 g_wqkv_hi[Lc*Dc*3*Dc], g_wqkv_lo[Lc*Dc*3*Dc];
__device__ bf16 g_wprj_hi[Lc*Dc*Dc],   g_wprj_lo[Lc*Dc*Dc];
__device__ bf16 g_wfc_hi [Lc*Dc*Ic],   g_wfc_lo [Lc*Dc*Ic];
__device__ bf16 g_wfp_hi [Lc*Ic*Dc],   g_wfp_lo [Lc*Ic*Dc];

// ---------------- utility ----------------------------------------------------
__inline__ __device__ float warp_sum(float v) {
    #pragma unroll
    for (int o = 16; o > 0; o >>= 1) v += __shfl_xor_sync(0xffffffffu, v, o);
    return v;
}
__device__ __forceinline__ void split2(float v, bf16& hi, bf16& lo) {
    hi = __float2bfloat16(v);
    lo = __float2bfloat16(v - __bfloat162float(hi));
}

// ---------------- weight split ------------------------------------------------
__global__ void split4_kernel(const float* __restrict__ src,
                              bf16* __restrict__ hi, bf16* __restrict__ lo, int n4) {
    int i = blockIdx.x * blockDim.x + threadIdx.x;
    if (i >= n4) return;
    float4 v = ((const float4*)src)[i];
    bf16 h0,l0,h1,l1,h2,l2,h3,l3;
    split2(v.x,h0,l0); split2(v.y,h1,l1); split2(v.z,h2,l2); split2(v.w,h3,l3);
    __nv_bfloat162* H = (__nv_bfloat162*)(hi + 4*(size_t)i);
    __nv_bfloat162* L = (__nv_bfloat162*)(lo + 4*(size_t)i);
    H[0] = __nv_bfloat162(h0,h1); H[1] = __nv_bfloat162(h2,h3);
    L[0] = __nv_bfloat162(l0,l1); L[1] = __nv_bfloat162(l2,l3);
}

// ---------------- layernorm (float4 vectorized) -------------------------------
template<bool SPLIT>
__global__ __launch_bounds__(256) void ln_kernel(
    const float* __restrict__ in, const float* __restrict__ w,
    const float* __restrict__ b, float* __restrict__ outf,
    bf16* __restrict__ outhi, bf16* __restrict__ outlo)
{
    int row = blockIdx.x;
    const float4* x4 = (const float4*)(in + (size_t)row * Dc);
    float4 xv = x4[threadIdx.x];
    float s  = xv.x + xv.y + xv.z + xv.w;
    float s2 = xv.x*xv.x + xv.y*xv.y + xv.z*xv.z + xv.w*xv.w;
    __shared__ float r1[8], r2[8];
    s = warp_sum(s); s2 = warp_sum(s2);
    int wid = threadIdx.x >> 5, lane = threadIdx.x & 31;
    if (lane == 0) { r1[wid] = s; r2[wid] = s2; }
    __syncthreads();
    if (wid == 0) {
        s  = (lane < 8) ? r1[lane] : 0.f;
        s2 = (lane < 8) ? r2[lane] : 0.f;
        s = warp_sum(s); s2 = warp_sum(s2);
        if (lane == 0) { r1[0] = s; r2[0] = s2; }
    }
    __syncthreads();
    float mean = r1[0] * (1.0f / Dc);
    float var  = r2[0] * (1.0f / Dc) - mean * mean;
    float inv  = rsqrtf(var + LN_EPS);
    float4 wv = ((const float4*)w)[threadIdx.x];
    float4 bv = ((const float4*)b)[threadIdx.x];
    float v0 = (xv.x - mean) * inv * wv.x + bv.x;
    float v1 = (xv.y - mean) * inv * wv.y + bv.y;
    float v2 = (xv.z - mean) * inv * wv.z + bv.z;
    float v3 = (xv.w - mean) * inv * wv.w + bv.w;
    if (SPLIT) {
        bf16 h0,l0,h1,l1,h2,l2,h3,l3;
        split2(v0,h0,l0); split2(v1,h1,l1); split2(v2,h2,l2); split2(v3,h3,l3);
        __nv_bfloat162 H[2] = {__nv_bfloat162(h0,h1), __nv_bfloat162(h2,h3)};
        __nv_bfloat162 L[2] = {__nv_bfloat162(l0,l1), __nv_bfloat162(l2,l3)};
        *(uint2*)(outhi + (size_t)row * Dc + threadIdx.x * 4) = *(uint2*)H;
        *(uint2*)(outlo + (size_t)row * Dc + threadIdx.x * 4) = *(uint2*)L;
    } else {
        ((float4*)(outf + (size_t)row * Dc))[threadIdx.x] = make_float4(v0, v1, v2, v3);
    }
}

// ---------------- MMA / ldmatrix helpers --------------------------------------
__device__ __forceinline__ void ldsm4(unsigned* r, unsigned addr) {
    asm volatile("ldmatrix.sync.aligned.m8n8.x4.shared.b16 {%0,%1,%2,%3},[%4];"
        : "=r"(r[0]), "=r"(r[1]), "=r"(r[2]), "=r"(r[3]) : "r"(addr));
}
__device__ __forceinline__ void ldsm4t(unsigned* r, unsigned addr) {
    asm volatile("ldmatrix.sync.aligned.m8n8.x4.trans.shared.b16 {%0,%1,%2,%3},[%4];"
        : "=r"(r[0]), "=r"(r[1]), "=r"(r[2]), "=r"(r[3]) : "r"(addr));
}
__device__ __forceinline__ void mma16816(float* c, const unsigned* a, const unsigned* b) {
    asm volatile("mma.sync.aligned.m16n8k16.row.col.f32.bf16.bf16.f32 "
        "{%0,%1,%2,%3},{%4,%5,%6,%7},{%8,%9},{%0,%1,%2,%3};"
        : "+f"(c[0]), "+f"(c[1]), "+f"(c[2]), "+f"(c[3])
        : "r"(a[0]), "r"(a[1]), "r"(a[2]), "r"(a[3]), "r"(b[0]), "r"(b[1]));
}
__device__ __forceinline__ void cp_async16(unsigned saddr, const void* g) {
    asm volatile("cp.async.cg.shared.global [%0], [%1], 16;" :: "r"(saddr), "l"(g));
}
__device__ __forceinline__ unsigned smem_u32(const void* p) {
    return (unsigned)__cvta_generic_to_shared(p);
}
__device__ __forceinline__ void packsplit(float x, float y, unsigned& hi, unsigned& lo) {
    bf16 hx = __float2bfloat16(x);
    bf16 hy = __float2bfloat16(y);
    bf16 lx = __float2bfloat16(x - __bfloat162float(hx));
    bf16 ly = __float2bfloat16(y - __bfloat162float(hy));
    __nv_bfloat162 H(hx, hy), L(lx, ly);
    hi = *(unsigned*)&H; lo = *(unsigned*)&L;
}

// ---------------- tensor-core GEMM (bf16x3, 3-stage ring, 1 barrier/iter) -----
// EPI 0: Cf = v+bias ; 1: Cf = res+v+bias ; 2: relu(v+bias)->split ; 3: (v+bias)->split
#define GBM 128
#define GBN 128
#define GBK 32
#define APAD 8
#define ASTRIDE (GBK + APAD)          // 40 elems (80B rows)
#define NBUF 3
#define SA_ELEMS (NBUF*2*GBM*ASTRIDE)    // 30720 bf16 = 61440 B
#define SB_BYTES_TILE (GBK * 256)        // 8192 B per (buf,p) tile
#define SB_BYTES (NBUF*2*SB_BYTES_TILE)  // 49152 B
#define GSMEM_BYTES (SA_ELEMS*2 + SB_BYTES)   // 110592 B  (2 CTAs/SM)

template<int EPI>
__global__ void __launch_bounds__(256, 2) gemm3_kernel(
    const bf16* __restrict__ Ahi, const bf16* __restrict__ Alo,
    const bf16* __restrict__ Bhi, const bf16* __restrict__ Blo,
    const float* __restrict__ bias, const float* __restrict__ res,
    float* __restrict__ Cf, bf16* __restrict__ Chi, bf16* __restrict__ Clo,
    int M, int N, int K)
{
    extern __shared__ __align__(16) bf16 smem[];
    bf16* sA = smem;
    char* sB = (char*)(smem + SA_ELEMS);
    const int tid = threadIdx.x;
    const int lane = tid & 31, wid = tid >> 5;
    const int wm = wid & 3, wn = wid >> 2;
    const int bm = blockIdx.y * GBM, bn = blockIdx.x * GBN;
    unsigned sA_base = smem_u32(sA);
    unsigned sB_base = smem_u32(sB);

    float acc[2][8][4] = {};

    auto fill = [&](int it, int buf) {
        int k0 = it * GBK;
        #pragma unroll
        for (int j = 0; j < 4; j++) {
            int c = tid + j * 256;
            int p = c >> 9, rem = c & 511;
            int r = rem >> 2, kc = (rem & 3) << 3;
            const bf16* src = (p ? Alo : Ahi) + (size_t)(bm + r) * K + k0 + kc;
            unsigned dst = sA_base + (unsigned)(((buf*2 + p)*GBM + r)*ASTRIDE + kc) * 2u;
            cp_async16(dst, src);
        }
        #pragma unroll
        for (int j = 0; j < 4; j++) {
            int c = tid + j * 256;
            int p = c >> 9, rem = c & 511;
            int k = rem >> 4, nc = rem & 15;
            const bf16* src = (p ? Blo : Bhi) + (size_t)(k0 + k) * N + bn + nc * 8;
            unsigned dst = sB_base + (unsigned)((buf*2 + p) * SB_BYTES_TILE
                          + k * 256 + ((nc ^ (k & 7)) << 4));
            cp_async16(dst, src);
        }
        asm volatile("cp.async.commit_group;" ::: "memory");
    };

    const int NIT = K >> 5;
    fill(0, 0);
    fill(1, 1);

    for (int it = 0; it < NIT; it++) {
        int buf = it % 3;
        // wait until stage `it` is resident (allow the one newer group pending)
        if (it + 1 < NIT) {
            asm volatile("cp.async.wait_group 1;" ::: "memory");
        } else {
            asm volatile("cp.async.wait_group 0;" ::: "memory");
        }
        __syncthreads();   // (a) stage-it data visible to all; (b) compute(it-1) done,
                           //     so buffer (it-1)%3 == (it+2)%3 is free to refill
        if (it + 2 < NIT) fill(it + 2, (it + 2) % 3);

        #pragma unroll
        for (int ks = 0; ks < 2; ks++) {
            unsigned afrag[2][2][4];
            int arow = wm * 32 + (lane & 15);
            int acol = ks * 16 + ((lane >> 4) << 3);
            #pragma unroll
            for (int mt = 0; mt < 2; mt++)
                #pragma unroll
                for (int p = 0; p < 2; p++)
                    ldsm4(afrag[mt][p],
                          sA_base + (unsigned)(((buf*2 + p)*GBM + arow + mt*16)*ASTRIDE + acol) * 2u);
            int brow = ks * 16 + (lane & 15);
            #pragma unroll
            for (int half = 0; half < 2; half++) {
                unsigned bfrag[2][4][2];
                #pragma unroll
                for (int ngh = 0; ngh < 2; ngh++) {
                    int ng = half * 2 + ngh;
                    int chunk = wn * 8 + ng * 2 + (lane >> 4);
                    #pragma unroll
                    for (int p = 0; p < 2; p++) {
                        unsigned addr = sB_base + (unsigned)((buf*2 + p) * SB_BYTES_TILE
                                      + brow * 256 + ((chunk ^ (brow & 7)) << 4));
                        unsigned r4[4];
                        ldsm4t(r4, addr);
                        bfrag[p][2*ngh][0]   = r4[0]; bfrag[p][2*ngh][1]   = r4[1];
                        bfrag[p][2*ngh+1][0] = r4[2]; bfrag[p][2*ngh+1][1] = r4[3];
                    }
                }
                #pragma unroll
                for (int mt = 0; mt < 2; mt++)
                    #pragma unroll
                    for (int nt = 0; nt < 4; nt++) {
                        float* a = acc[mt][half*4 + nt];
                        mma16816(a, afrag[mt][0], bfrag[0][nt]);
                        mma16816(a, afrag[mt][0], bfrag[1][nt]);
                        mma16816(a, afrag[mt][1], bfrag[0][nt]);
                    }
            }
        }
    }

    // epilogue
    #pragma unroll
    for (int mt = 0; mt < 2; mt++) {
        #pragma unroll
        for (int nt = 0; nt < 8; nt++) {
            int r0 = bm + wm * 32 + mt * 16 + (lane >> 2);
            int c0 = bn + wn * 64 + nt * 8 + ((lane & 3) << 1);
            #pragma unroll
            for (int hh = 0; hh < 2; hh++) {
                int rr = r0 + hh * 8;
                #pragma unroll
                for (int cc = 0; cc < 2; cc++) {
                    int col = c0 + cc;
                    float v = acc[mt][nt][hh*2 + cc] + bias[col];
                    size_t idx = (size_t)rr * N + col;
                    if (EPI == 0) {
                        Cf[idx] = v;
                    } else if (EPI == 1) {
                        Cf[idx] = res[idx] + v;
                    } else {
                        if (EPI == 2) v = fmaxf(v, 0.f);
                        bf16 vh, vl; split2(v, vh, vl);
                        Chi[idx] = vh; Clo[idx] = vl;
                    }
                }
            }
        }
    }
}

// ---------------- HMMA flash attention (bf16x3) -------------------------------
#define AQ 128
#define AKT 64
#define QSTR 72
#define ASMEM_BYTES (2*128*QSTR*2 + 4*64*QSTR*2 + 256)

__global__ void __launch_bounds__(256, 1) attn_mma_kernel(
    const bf16* __restrict__ qkv_hi, const bf16* __restrict__ qkv_lo,
    const float* __restrict__ amask,
    bf16* __restrict__ ctxhi, bf16* __restrict__ ctxlo)
{
    extern __shared__ __align__(16) char asmem[];
    bf16* sQh = (bf16*)asmem;
    bf16* sQl = sQh + 128*QSTR;
    bf16* sKh = sQl + 128*QSTR;
    bf16* sKl = sKh + 64*QSTR;
    bf16* sVh = sKl + 64*QSTR;
    bf16* sVl = sVh + 64*QSTR;
    float* skm = (float*)(sVl + 64*QSTR);

    const int tid = threadIdx.x, lane = tid & 31, w = tid >> 5;
    const int bh = blockIdx.y, b = bh >> 4, hh = bh & 15;
    const int q0 = blockIdx.x * AQ;
    const float scale = 0.125f;

    const size_t rstr = 3 * Dc;
    const bf16* qh = qkv_hi + (size_t)b * Tc * rstr + hh * HD;
    const bf16* ql = qkv_lo + (size_t)b * Tc * rstr + hh * HD;
    const bf16* kh = qh + Dc;  const bf16* kl = ql + Dc;
    const bf16* vh = qh + 2*Dc; const bf16* vl = ql + 2*Dc;

    #pragma unroll
    for (int j = 0; j < 8; j++) {
        int c = tid + j * 256;
        int p = c >> 10, rem = c & 1023;
        int row = rem >> 3, ch = rem & 7;
        *(uint4*)((p ? sQl : sQh) + row * QSTR + ch * 8) =
            *(const uint4*)((p ? ql : qh) + (size_t)(q0 + row) * rstr + ch * 8);
    }
    __syncthreads();

    const unsigned qb_h = smem_u32(sQh), qb_l = smem_u32(sQl);
    const unsigned kb_h = smem_u32(sKh), kb_l = smem_u32(sKl);
    const unsigned vb_h = smem_u32(sVh), vb_l = smem_u32(sVl);

    unsigned aQh[4][4], aQl[4][4];
    {
        int arow = w * 16 + (lane & 15);
        #pragma unroll
        for (int g = 0; g < 4; g++) {
            int acol = g * 16 + ((lane >> 4) << 3);
            unsigned off = (unsigned)(arow * QSTR + acol) * 2u;
            ldsm4(aQh[g], qb_h + off);
            ldsm4(aQl[g], qb_l + off);
        }
    }

    float acc[8][4];
    #pragma unroll
    for (int nt = 0; nt < 8; nt++)
        #pragma unroll
        for (int e = 0; e < 4; e++) acc[nt][e] = 0.f;
    float m0 = -1e30f, m1 = -1e30f, l0 = 0.f, l1 = 0.f;

    const int qg0 = q0 + w * 16 + (lane >> 2);
    const int ncol = (lane & 3) << 1;
    const int kn_l = (lane & 7) + ((lane >> 4) << 3);
    const int kkoff = ((lane >> 3) & 1) << 3;

    const int nkt = 2 * blockIdx.x + 2;
    for (int kt = 0; kt < nkt; kt++) {
        int kk0 = kt * AKT;
        __syncthreads();
        #pragma unroll
        for (int j = 0; j < 8; j++) {
            int c = tid + j * 256;
            int arr = c >> 9, rem = c & 511;
            int row = rem >> 3, ch = rem & 7;
            const bf16* gp = (arr == 0) ? kh : (arr == 1) ? kl : (arr == 2) ? vh : vl;
            bf16* sp = (arr == 0) ? sKh : (arr == 1) ? sKl : (arr == 2) ? sVh : sVl;
            *(uint4*)(sp + row * QSTR + ch * 8) =
                *(const uint4*)(gp + (size_t)(kk0 + row) * rstr + ch * 8);
        }
        if (tid < 64) skm[tid] = (1.0f - amask[b * Tc + kk0 + tid]) * MASK_BIAS;
        __syncthreads();

        float S[8][4];
        #pragma unroll
        for (int nt = 0; nt < 8; nt++)
            #pragma unroll
            for (int e = 0; e < 4; e++) S[nt][e] = 0.f;

        #pragma unroll
        for (int g = 0; g < 4; g++) {
            unsigned bKh[8][2], bKl[8][2];
            #pragma unroll
            for (int np = 0; np < 4; np++) {
                unsigned off = (unsigned)((np * 16 + kn_l) * QSTR + g * 16 + kkoff) * 2u;
                unsigned r4[4];
                ldsm4(r4, kb_h + off);
                bKh[2*np][0] = r4[0]; bKh[2*np][1] = r4[1];
                bKh[2*np+1][0] = r4[2]; bKh[2*np+1][1] = r4[3];
                ldsm4(r4, kb_l + off);
                bKl[2*np][0] = r4[0]; bKl[2*np][1] = r4[1];
                bKl[2*np+1][0] = r4[2]; bKl[2*np+1][1] = r4[3];
            }
            #pragma unroll
            for (int nt = 0; nt < 8; nt++) {
                mma16816(S[nt], aQh[g], bKh[nt]);
                mma16816(S[nt], aQh[g], bKl[nt]);
                mma16816(S[nt], aQl[g], bKh[nt]);
            }
        }

        float tmax0 = -1e30f, tmax1 = -1e30f;
        #pragma unroll
        for (int nt = 0; nt < 8; nt++) {
            int n0 = kk0 + nt * 8 + ncol;
            float km0 = skm[nt * 8 + ncol], km1 = skm[nt * 8 + ncol + 1];
            float s0 = (n0     <= qg0    ) ? S[nt][0] * scale + km0 : -1e30f;
            float s1 = (n0 + 1 <= qg0    ) ? S[nt][1] * scale + km1 : -1e30f;
            float s2 = (n0     <= qg0 + 8) ? S[nt][2] * scale + km0 : -1e30f;
            float s3 = (n0 + 1 <= qg0 + 8) ? S[nt][3] * scale + km1 : -1e30f;
            S[nt][0] = s0; S[nt][1] = s1; S[nt][2] = s2; S[nt][3] = s3;
            tmax0 = fmaxf(tmax0, fmaxf(s0, s1));
            tmax1 = fmaxf(tmax1, fmaxf(s2, s3));
        }
        tmax0 = fmaxf(tmax0, __shfl_xor_sync(0xffffffffu, tmax0, 1));
        tmax0 = fmaxf(tmax0, __shfl_xor_sync(0xffffffffu, tmax0, 2));
        tmax1 = fmaxf(tmax1, __shfl_xor_sync(0xffffffffu, tmax1, 1));
        tmax1 = fmaxf(tmax1, __shfl_xor_sync(0xffffffffu, tmax1, 2));

        float nm0 = fmaxf(m0, tmax0), nm1 = fmaxf(m1, tmax1);
        float cr0 = __expf(m0 - nm0), cr1 = __expf(m1 - nm1);
        m0 = nm0; m1 = nm1;

        float sum0 = 0.f, sum1 = 0.f;
        #pragma unroll
        for (int nt = 0; nt < 8; nt++) {
            float p0 = __expf(S[nt][0] - m0);
            float p1 = __expf(S[nt][1] - m0);
            float p2 = __expf(S[nt][2] - m1);
            float p3 = __expf(S[nt][3] - m1);
            S[nt][0] = p0; S[nt][1] = p1; S[nt][2] = p2; S[nt][3] = p3;
            sum0 += p0 + p1; sum1 += p2 + p3;
        }
        sum0 += __shfl_xor_sync(0xffffffffu, sum0, 1);
        sum0 += __shfl_xor_sync(0xffffffffu, sum0, 2);
        sum1 += __shfl_xor_sync(0xffffffffu, sum1, 1);
        sum1 += __shfl_xor_sync(0xffffffffu, sum1, 2);
        l0 = l0 * cr0 + sum0;
        l1 = l1 * cr1 + sum1;
        #pragma unroll
        for (int nt = 0; nt < 8; nt++) {
            acc[nt][0] *= cr0; acc[nt][1] *= cr0;
            acc[nt][2] *= cr1; acc[nt][3] *= cr1;
        }

        #pragma unroll
        for (int g = 0; g < 4; g++) {
            unsigned aPh[4], aPl[4];
            packsplit(S[2*g][0],   S[2*g][1],   aPh[0], aPl[0]);
            packsplit(S[2*g][2],   S[2*g][3],   aPh[1], aPl[1]);
            packsplit(S[2*g+1][0], S[2*g+1][1], aPh[2], aPl[2]);
            packsplit(S[2*g+1][2], S[2*g+1][3], aPh[3], aPl[3]);
            unsigned bVh[8][2], bVl[8][2];
            int brow = g * 16 + (lane & 15);
            #pragma unroll
            for (int np = 0; np < 4; np++) {
                int bcol = np * 16 + ((lane >> 4) << 3);
                unsigned off = (unsigned)(brow * QSTR + bcol) * 2u;
                unsigned r4[4];
                ldsm4t(r4, vb_h + off);
                bVh[2*np][0] = r4[0]; bVh[2*np][1] = r4[1];
                bVh[2*np+1][0] = r4[2]; bVh[2*np+1][1] = r4[3];
                ldsm4t(r4, vb_l + off);
                bVl[2*np][0] = r4[0]; bVl[2*np][1] = r4[1];
                bVl[2*np+1][0] = r4[2]; bVl[2*np+1][1] = r4[3];
            }
            #pragma unroll
            for (int nt = 0; nt < 8; nt++) {
                mma16816(acc[nt], aPh, bVh[nt]);
                mma16816(acc[nt], aPh, bVl[nt]);
                mma16816(acc[nt], aPl, bVh[nt]);
            }
        }
    }

    float il0 = 1.0f / l0, il1 = 1.0f / l1;
    int row0 = q0 + w * 16 + (lane >> 2);
    size_t o0 = ((size_t)(b * Tc + row0)) * Dc + hh * HD + ncol;
    size_t o1 = ((size_t)(b * Tc + row0 + 8)) * Dc + hh * HD + ncol;
    #pragma unroll
    for (int nt = 0; nt < 8; nt++) {
        float v0 = acc[nt][0] * il0, v1 = acc[nt][1] * il0;
        float v2 = acc[nt][2] * il1, v3 = acc[nt][3] * il1;
        bf16 h0,lo0,h1,lo1,h2,lo2,h3,lo3;
        split2(v0,h0,lo0); split2(v1,h1,lo1); split2(v2,h2,lo2); split2(v3,h3,lo3);
        *(__nv_bfloat162*)(ctxhi + o0 + nt*8) = __nv_bfloat162(h0, h1);
        *(__nv_bfloat162*)(ctxlo + o0 + nt*8) = __nv_bfloat162(lo0, lo1);
        *(__nv_bfloat162*)(ctxhi + o1 + nt*8) = __nv_bfloat162(h2, h3);
        *(__nv_bfloat162*)(ctxlo + o1 + nt*8) = __nv_bfloat162(lo2, lo3);
    }
}

// ---------------- launch -----------------------------------------------------
extern "C" void kernel_launch(void* const* d_in, const int* in_sizes, int n_in,
                              void* d_out, int out_size)
{
    const float* emb    = (const float*)d_in[0];
    const float* amask  = (const float*)d_in[1];
    const float* ln1_w  = (const float*)d_in[2];
    const float* ln1_b  = (const float*)d_in[3];
    const float* attn_w = (const float*)d_in[4];
    const float* attn_b = (const float*)d_in[5];
    const float* proj_w = (const float*)d_in[6];
    const float* proj_b = (const float*)d_in[7];
    const float* ln2_w  = (const float*)d_in[8];
    const float* ln2_b  = (const float*)d_in[9];
    const float* fc_w   = (const float*)d_in[10];
    const float* fc_b   = (const float*)d_in[11];
    const float* fcp_w  = (const float*)d_in[12];
    const float* fcp_b  = (const float*)d_in[13];
    const float* lnf_w  = (const float*)d_in[14];
    const float* lnf_b  = (const float*)d_in[15];
    float* out = (float*)d_out;

    float* h;
    bf16 *qhi, *qlo, *xhi, *xlo, *chi, *clo, *ahi, *alo;
    bf16 *wq_h, *wq_l, *wp_h, *wp_l, *wf_h, *wf_l, *wg_h, *wg_l;
    cudaGetSymbolAddress((void**)&h,    g_h);
    cudaGetSymbolAddress((void**)&qhi,  g_qhi);  cudaGetSymbolAddress((void**)&qlo, g_qlo);
    cudaGetSymbolAddress((void**)&xhi,  g_xhi);  cudaGetSymbolAddress((void**)&xlo, g_xlo);
    cudaGetSymbolAddress((void**)&chi,  g_chi);  cudaGetSymbolAddress((void**)&clo, g_clo);
    cudaGetSymbolAddress((void**)&ahi,  g_ahi);  cudaGetSymbolAddress((void**)&alo, g_alo);
    cudaGetSymbolAddress((void**)&wq_h, g_wqkv_hi); cudaGetSymbolAddress((void**)&wq_l, g_wqkv_lo);
    cudaGetSymbolAddress((void**)&wp_h, g_wprj_hi); cudaGetSymbolAddress((void**)&wp_l, g_wprj_lo);
    cudaGetSymbolAddress((void**)&wf_h, g_wfc_hi);  cudaGetSymbolAddress((void**)&wf_l, g_wfc_lo);
    cudaGetSymbolAddress((void**)&wg_h, g_wfp_hi);  cudaGetSymbolAddress((void**)&wg_l, g_wfp_lo);

    cudaFuncSetAttribute(gemm3_kernel<0>, cudaFuncAttributeMaxDynamicSharedMemorySize, GSMEM_BYTES);
    cudaFuncSetAttribute(gemm3_kernel<1>, cudaFuncAttributeMaxDynamicSharedMemorySize, GSMEM_BYTES);
    cudaFuncSetAttribute(gemm3_kernel<2>, cudaFuncAttributeMaxDynamicSharedMemorySize, GSMEM_BYTES);
    cudaFuncSetAttribute(gemm3_kernel<3>, cudaFuncAttributeMaxDynamicSharedMemorySize, GSMEM_BYTES);
    cudaFuncSetAttribute(attn_mma_kernel, cudaFuncAttributeMaxDynamicSharedMemorySize, ASMEM_BYTES);

    // weight splits [K,N] hi/lo
    { int n4 = Lc*Dc*3*Dc/4; split4_kernel<<<(n4+255)/256, 256>>>(attn_w, wq_h, wq_l, n4); }
    { int n4 = Lc*Dc*Dc/4;   split4_kernel<<<(n4+255)/256, 256>>>(proj_w, wp_h, wp_l, n4); }
    { int n4 = Lc*Dc*Ic/4;   split4_kernel<<<(n4+255)/256, 256>>>(fc_w,   wf_h, wf_l, n4); }
    { int n4 = Lc*Ic*Dc/4;   split4_kernel<<<(n4+255)/256, 256>>>(fcp_w,  wg_h, wg_l, n4); }

    for (int l = 0; l < Lc; l++) {
        const float* hin = (l == 0) ? emb : h;   // layer-0 reads embeds directly
        // x = ln1(hin) -> split
        ln_kernel<true><<<ROWS, 256>>>(hin, ln1_w + (size_t)l*Dc, ln1_b + (size_t)l*Dc,
                                       nullptr, xhi, xlo);
        // qkv = x @ attn_w + attn_b  -> bf16 hi/lo
        gemm3_kernel<3><<<dim3(3*Dc/GBN, ROWS/GBM), 256, GSMEM_BYTES>>>(
            xhi, xlo, wq_h + (size_t)l*Dc*3*Dc, wq_l + (size_t)l*Dc*3*Dc,
            attn_b + (size_t)l*3*Dc, nullptr, nullptr, qhi, qlo,
            ROWS, 3*Dc, Dc);
        // ctx = attention(qkv) -> split
        attn_mma_kernel<<<dim3(Tc/AQ, Bc*Hc), 256, ASMEM_BYTES>>>(qhi, qlo, amask, chi, clo);
        // h = hin + ctx @ proj_w + proj_b
        gemm3_kernel<1><<<dim3(Dc/GBN, ROWS/GBM), 256, GSMEM_BYTES>>>(
            chi, clo, wp_h + (size_t)l*Dc*Dc, wp_l + (size_t)l*Dc*Dc,
            proj_b + (size_t)l*Dc, hin, h, nullptr, nullptr,
            ROWS, Dc, Dc);
        // x = ln2(h) -> split
        ln_kernel<true><<<ROWS, 256>>>(h, ln2_w + (size_t)l*Dc, ln2_b + (size_t)l*Dc,
                                       nullptr, xhi, xlo);
        // act = relu(x @ fc_w + fc_b) -> split
        gemm3_kernel<2><<<dim3(Ic/GBN, ROWS/GBM), 256, GSMEM_BYTES>>>(
            xhi, xlo, wf_h + (size_t)l*Dc*Ic, wf_l + (size_t)l*Dc*Ic,
            fc_b + (size_t)l*Ic, nullptr, nullptr, ahi, alo,
            ROWS, Ic, Dc);
        // h = h + act @ fcp_w + fcp_b
        gemm3_kernel<1><<<dim3(Dc/GBN, ROWS/GBM), 256, GSMEM_BYTES>>>(
            ahi, alo, wg_h + (size_t)l*Ic*Dc, wg_l + (size_t)l*Ic*Dc,
            fcp_b + (size_t)l*Dc, h, h, nullptr, nullptr,
            ROWS, Dc, Ic);
    }
    // out = ln_f(h) (fp32)
    ln_kernel<false><<<ROWS, 256>>>(h, lnf_w, lnf_b, out, nullptr, nullptr);
}

// round 16
// speedup vs baseline: 1.4838x; 1.4838x over previous
#include <cuda_runtime.h>
#include <cuda_fp16.h>
#include <math.h>
#include <stdint.h>

// Problem constants
#define Bc 2
#define Tc 2048
#define Dc 1024
#define Hc 16
#define Lc 8
#define Ic 4096
#define HD 64
#define ROWS (Bc*Tc)    // 4096 token rows
#define LN_EPS 1e-5f
#define MASK_BIAS -10000.0f

typedef __half f16;

// ---------------- scratch (static device globals; no allocation) -------------
__device__ float g_h[ROWS * Dc];            // residual stream (fp32)
__device__ f16  g_qhi[ROWS * 3 * Dc], g_qlo[ROWS * 3 * Dc];  // qkv split
__device__ f16  g_x [ROWS * Dc];            // LN output (single fp16)
__device__ f16  g_ctx[ROWS * Dc];           // attention ctx (single fp16)
__device__ f16  g_act[ROWS * Ic];           // ffn inner (single fp16)
// weight splits [K, N] layout, fp16 hi/lo
__device__ f16 g_wqkv_hi[Lc*Dc*3*Dc], g_wqkv_lo[Lc*Dc*3*Dc];
__device__ f16 g_wprj_hi[Lc*Dc*Dc],   g_wprj_lo[Lc*Dc*Dc];
__device__ f16 g_wfc_hi [Lc*Dc*Ic],   g_wfc_lo [Lc*Dc*Ic];
__device__ f16 g_wfp_hi [Lc*Ic*Dc],   g_wfp_lo [Lc*Ic*Dc];

// ---------------- utility ----------------------------------------------------
__inline__ __device__ float warp_sum(float v) {
    #pragma unroll
    for (int o = 16; o > 0; o >>= 1) v += __shfl_xor_sync(0xffffffffu, v, o);
    return v;
}
__device__ __forceinline__ void split2h(float v, f16& hi, f16& lo) {
    hi = __float2half_rn(v);
    lo = __float2half_rn(v - __half2float(hi));
}
__device__ __forceinline__ unsigned packh2(float x, float y) {
    __half2 h = __floats2half2_rn(x, y);
    return *(unsigned*)&h;
}

// ---------------- weight split ------------------------------------------------
__global__ void split4_kernel(const float* __restrict__ src,
                              f16* __restrict__ hi, f16* __restrict__ lo, int n4) {
    int i = blockIdx.x * blockDim.x + threadIdx.x;
    if (i >= n4) return;
    float4 v = ((const float4*)src)[i];
    f16 h0,l0,h1,l1,h2,l2,h3,l3;
    split2h(v.x,h0,l0); split2h(v.y,h1,l1); split2h(v.z,h2,l2); split2h(v.w,h3,l3);
    __half2* H = (__half2*)(hi + 4*(size_t)i);
    __half2* L = (__half2*)(lo + 4*(size_t)i);
    H[0] = __half2(h0,h1); H[1] = __half2(h2,h3);
    L[0] = __half2(l0,l1); L[1] = __half2(l2,l3);
}

// ---------------- layernorm (float4 vectorized) -------------------------------
template<bool TOF16>
__global__ __launch_bounds__(256) void ln_kernel(
    const float* __restrict__ in, const float* __restrict__ w,
    const float* __restrict__ b, float* __restrict__ outf,
    f16* __restrict__ outh)
{
    int row = blockIdx.x;
    const float4* x4 = (const float4*)(in + (size_t)row * Dc);
    float4 xv = x4[threadIdx.x];
    float s  = xv.x + xv.y + xv.z + xv.w;
    float s2 = xv.x*xv.x + xv.y*xv.y + xv.z*xv.z + xv.w*xv.w;
    __shared__ float r1[8], r2[8];
    s = warp_sum(s); s2 = warp_sum(s2);
    int wid = threadIdx.x >> 5, lane = threadIdx.x & 31;
    if (lane == 0) { r1[wid] = s; r2[wid] = s2; }
    __syncthreads();
    if (wid == 0) {
        s  = (lane < 8) ? r1[lane] : 0.f;
        s2 = (lane < 8) ? r2[lane] : 0.f;
        s = warp_sum(s); s2 = warp_sum(s2);
        if (lane == 0) { r1[0] = s; r2[0] = s2; }
    }
    __syncthreads();
    float mean = r1[0] * (1.0f / Dc);
    float var  = r2[0] * (1.0f / Dc) - mean * mean;
    float inv  = rsqrtf(var + LN_EPS);
    float4 wv = ((const float4*)w)[threadIdx.x];
    float4 bv = ((const float4*)b)[threadIdx.x];
    float v0 = (xv.x - mean) * inv * wv.x + bv.x;
    float v1 = (xv.y - mean) * inv * wv.y + bv.y;
    float v2 = (xv.z - mean) * inv * wv.z + bv.z;
    float v3 = (xv.w - mean) * inv * wv.w + bv.w;
    if (TOF16) {
        uint2 o;
        o.x = packh2(v0, v1);
        o.y = packh2(v2, v3);
        *(uint2*)(outh + (size_t)row * Dc + threadIdx.x * 4) = o;
    } else {
        ((float4*)(outf + (size_t)row * Dc))[threadIdx.x] = make_float4(v0, v1, v2, v3);
    }
}

// ---------------- MMA / ldmatrix helpers --------------------------------------
__device__ __forceinline__ void ldsm4(unsigned* r, unsigned addr) {
    asm volatile("ldmatrix.sync.aligned.m8n8.x4.shared.b16 {%0,%1,%2,%3},[%4];"
        : "=r"(r[0]), "=r"(r[1]), "=r"(r[2]), "=r"(r[3]) : "r"(addr));
}
__device__ __forceinline__ void ldsm4t(unsigned* r, unsigned addr) {
    asm volatile("ldmatrix.sync.aligned.m8n8.x4.trans.shared.b16 {%0,%1,%2,%3},[%4];"
        : "=r"(r[0]), "=r"(r[1]), "=r"(r[2]), "=r"(r[3]) : "r"(addr));
}
__device__ __forceinline__ void mma16816(float* c, const unsigned* a, const unsigned* b) {
    asm volatile("mma.sync.aligned.m16n8k16.row.col.f32.f16.f16.f32 "
        "{%0,%1,%2,%3},{%4,%5,%6,%7},{%8,%9},{%0,%1,%2,%3};"
        : "+f"(c[0]), "+f"(c[1]), "+f"(c[2]), "+f"(c[3])
        : "r"(a[0]), "r"(a[1]), "r"(a[2]), "r"(a[3]), "r"(b[0]), "r"(b[1]));
}
__device__ __forceinline__ void cp_async16(unsigned saddr, const void* g) {
    asm volatile("cp.async.cg.shared.global [%0], [%1], 16;" :: "r"(saddr), "l"(g));
}
__device__ __forceinline__ unsigned smem_u32(const void* p) {
    return (unsigned)__cvta_generic_to_shared(p);
}

// ---------------- tensor-core GEMM (fp16x2: A single, W hi/lo) ----------------
// C = A @ (Wh + Wl) + bias.  EPI 1: Cf = res+v ; 2: relu(v)->f16 ; 3: v->f16 hi/lo
#define GBM 128
#define GBN 128
#define GBK 32
#define APAD 8
#define ASTRIDE (GBK + APAD)          // 40 elems (80B rows)
#define SA_ELEMS (2*GBM*ASTRIDE)      // 10240 f16 = 20480 B (2 bufs, single A)
#define SB_BYTES_TILE (GBK * 256)     // 8192 B per (buf,dig) tile
#define SB_BYTES (2*2*SB_BYTES_TILE)  // 32768 B
#define GSMEM_BYTES (SA_ELEMS*2 + SB_BYTES)   // 53248 B

template<int EPI>
__global__ void __launch_bounds__(256, 2) gemm2_kernel(
    const f16* __restrict__ A,
    const f16* __restrict__ Bhi, const f16* __restrict__ Blo,
    const float* __restrict__ bias, const float* __restrict__ res,
    float* __restrict__ Cf, f16* __restrict__ Chi, f16* __restrict__ Clo,
    int M, int N, int K)
{
    extern __shared__ __align__(16) f16 smem[];
    f16* sA = smem;
    char* sB = (char*)(smem + SA_ELEMS);
    const int tid = threadIdx.x;
    const int lane = tid & 31, wid = tid >> 5;
    const int wm = wid & 3, wn = wid >> 2;
    const int bm = blockIdx.y * GBM, bn = blockIdx.x * GBN;
    unsigned sA_base = smem_u32(sA);
    unsigned sB_base = smem_u32(sB);

    float acc[2][8][4] = {};

    auto issue = [&](int it, int buf) {
        int k0 = it * GBK;
        #pragma unroll
        for (int j = 0; j < 2; j++) {          // A: 512 16B chunks
            int c = tid + j * 256;
            int r = c >> 2, kc = (c & 3) << 3;
            const f16* src = A + (size_t)(bm + r) * K + k0 + kc;
            unsigned dst = sA_base + (unsigned)((buf*GBM + r)*ASTRIDE + kc) * 2u;
            cp_async16(dst, src);
        }
        #pragma unroll
        for (int j = 0; j < 4; j++) {          // B: 1024 16B chunks (hi+lo)
            int c = tid + j * 256;
            int p = c >> 9, rem = c & 511;
            int k = rem >> 4, nc = rem & 15;
            const f16* src = (p ? Blo : Bhi) + (size_t)(k0 + k) * N + bn + nc * 8;
            unsigned dst = sB_base + (unsigned)((buf*2 + p) * SB_BYTES_TILE
                          + k * 256 + ((nc ^ (k & 7)) << 4));
            cp_async16(dst, src);
        }
        asm volatile("cp.async.commit_group;" ::: "memory");
    };

    issue(0, 0);
    const int NIT = K >> 5;
    for (int it = 0; it < NIT; it++) {
        int buf = it & 1;
        if (it + 1 < NIT) {
            issue(it + 1, buf ^ 1);
            asm volatile("cp.async.wait_group 1;" ::: "memory");
        } else {
            asm volatile("cp.async.wait_group 0;" ::: "memory");
        }
        __syncthreads();
        #pragma unroll
        for (int ks = 0; ks < 2; ks++) {
            unsigned afrag[2][4];
            int arow = wm * 32 + (lane & 15);
            int acol = ks * 16 + ((lane >> 4) << 3);
            #pragma unroll
            for (int mt = 0; mt < 2; mt++)
                ldsm4(afrag[mt],
                      sA_base + (unsigned)((buf*GBM + arow + mt*16)*ASTRIDE + acol) * 2u);
            int brow = ks * 16 + (lane & 15);
            #pragma unroll
            for (int half = 0; half < 2; half++) {
                unsigned bfrag[2][4][2];
                #pragma unroll
                for (int ngh = 0; ngh < 2; ngh++) {
                    int ng = half * 2 + ngh;
                    int chunk = wn * 8 + ng * 2 + (lane >> 4);
                    #pragma unroll
                    for (int p = 0; p < 2; p++) {
                        unsigned addr = sB_base + (unsigned)((buf*2 + p) * SB_BYTES_TILE
                                      + brow * 256 + ((chunk ^ (brow & 7)) << 4));
                        unsigned r4[4];
                        ldsm4t(r4, addr);
                        bfrag[p][2*ngh][0]   = r4[0]; bfrag[p][2*ngh][1]   = r4[1];
                        bfrag[p][2*ngh+1][0] = r4[2]; bfrag[p][2*ngh+1][1] = r4[3];
                    }
                }
                #pragma unroll
                for (int mt = 0; mt < 2; mt++)
                    #pragma unroll
                    for (int nt = 0; nt < 4; nt++) {
                        float* a = acc[mt][half*4 + nt];
                        mma16816(a, afrag[mt], bfrag[0][nt]);   // A*Wh
                        mma16816(a, afrag[mt], bfrag[1][nt]);   // A*Wl
                    }
            }
        }
        __syncthreads();
    }

    // epilogue
    #pragma unroll
    for (int mt = 0; mt < 2; mt++) {
        #pragma unroll
        for (int nt = 0; nt < 8; nt++) {
            int r0 = bm + wm * 32 + mt * 16 + (lane >> 2);
            int c0 = bn + wn * 64 + nt * 8 + ((lane & 3) << 1);
            #pragma unroll
            for (int hh = 0; hh < 2; hh++) {
                int rr = r0 + hh * 8;
                #pragma unroll
                for (int cc = 0; cc < 2; cc++) {
                    int col = c0 + cc;
                    float v = acc[mt][nt][hh*2 + cc] + bias[col];
                    size_t idx = (size_t)rr * N + col;
                    if (EPI == 1) {
                        Cf[idx] = res[idx] + v;
                    } else if (EPI == 2) {
                        Chi[idx] = __float2half_rn(fmaxf(v, 0.f));
                    } else {  // EPI 3: hi/lo split (qkv)
                        f16 vh, vl; split2h(v, vh, vl);
                        Chi[idx] = vh; Clo[idx] = vl;
                    }
                }
            }
        }
    }
}

// ---------------- HMMA flash attention (fp16x2) -------------------------------
// Q single fp16 (=hi digit), K/V hi+lo; S and P*V use 2 MMA terms.
#define AQ 128
#define AKT 64
#define QSTR 72
#define ASMEM_BYTES ((128*QSTR + 4*64*QSTR)*2 + 256)

__global__ void __launch_bounds__(256, 1) attn_mma_kernel(
    const f16* __restrict__ qkv_hi, const f16* __restrict__ qkv_lo,
    const float* __restrict__ amask,
    f16* __restrict__ ctx)
{
    extern __shared__ __align__(16) char asmem[];
    f16* sQ  = (f16*)asmem;
    f16* sKh = sQ  + 128*QSTR;
    f16* sKl = sKh + 64*QSTR;
    f16* sVh = sKl + 64*QSTR;
    f16* sVl = sVh + 64*QSTR;
    float* skm = (float*)(sVl + 64*QSTR);

    const int tid = threadIdx.x, lane = tid & 31, w = tid >> 5;
    const int bh = blockIdx.y, b = bh >> 4, hh = bh & 15;
    const int q0 = blockIdx.x * AQ;
    const float scale = 0.125f;

    const size_t rstr = 3 * Dc;
    const f16* qh = qkv_hi + (size_t)b * Tc * rstr + hh * HD;
    const f16* kh = qh + Dc;
    const f16* kl = qkv_lo + (size_t)b * Tc * rstr + hh * HD + Dc;
    const f16* vh = qh + 2*Dc;
    const f16* vl = kl + Dc;

    // load Q tile (single): 1024 16B chunks
    #pragma unroll
    for (int j = 0; j < 4; j++) {
        int c = tid + j * 256;
        int row = c >> 3, ch = c & 7;
        *(uint4*)(sQ + row * QSTR + ch * 8) =
            *(const uint4*)(qh + (size_t)(q0 + row) * rstr + ch * 8);
    }
    __syncthreads();

    const unsigned qb  = smem_u32(sQ);
    const unsigned kb_h = smem_u32(sKh), kb_l = smem_u32(sKl);
    const unsigned vb_h = smem_u32(sVh), vb_l = smem_u32(sVl);

    unsigned aQ[4][4];
    {
        int arow = w * 16 + (lane & 15);
        #pragma unroll
        for (int g = 0; g < 4; g++) {
            int acol = g * 16 + ((lane >> 4) << 3);
            ldsm4(aQ[g], qb + (unsigned)(arow * QSTR + acol) * 2u);
        }
    }

    float acc[8][4];
    #pragma unroll
    for (int nt = 0; nt < 8; nt++)
        #pragma unroll
        for (int e = 0; e < 4; e++) acc[nt][e] = 0.f;
    float m0 = -1e30f, m1 = -1e30f, l0 = 0.f, l1 = 0.f;

    const int qg0 = q0 + w * 16 + (lane >> 2);
    const int ncol = (lane & 3) << 1;
    const int kn_l = (lane & 7) + ((lane >> 4) << 3);
    const int kkoff = ((lane >> 3) & 1) << 3;

    const int nkt = 2 * blockIdx.x + 2;
    for (int kt = 0; kt < nkt; kt++) {
        int kk0 = kt * AKT;
        __syncthreads();
        #pragma unroll
        for (int j = 0; j < 8; j++) {
            int c = tid + j * 256;
            int arr = c >> 9, rem = c & 511;
            int row = rem >> 3, ch = rem & 7;
            const f16* gp = (arr == 0) ? kh : (arr == 1) ? kl : (arr == 2) ? vh : vl;
            f16* sp = (arr == 0) ? sKh : (arr == 1) ? sKl : (arr == 2) ? sVh : sVl;
            *(uint4*)(sp + row * QSTR + ch * 8) =
                *(const uint4*)(gp + (size_t)(kk0 + row) * rstr + ch * 8);
        }
        if (tid < 64) skm[tid] = (1.0f - amask[b * Tc + kk0 + tid]) * MASK_BIAS;
        __syncthreads();

        float S[8][4];
        #pragma unroll
        for (int nt = 0; nt < 8; nt++)
            #pragma unroll
            for (int e = 0; e < 4; e++) S[nt][e] = 0.f;

        #pragma unroll
        for (int g = 0; g < 4; g++) {
            unsigned bKh[8][2], bKl[8][2];
            #pragma unroll
            for (int np = 0; np < 4; np++) {
                unsigned off = (unsigned)((np * 16 + kn_l) * QSTR + g * 16 + kkoff) * 2u;
                unsigned r4[4];
                ldsm4(r4, kb_h + off);
                bKh[2*np][0] = r4[0]; bKh[2*np][1] = r4[1];
                bKh[2*np+1][0] = r4[2]; bKh[2*np+1][1] = r4[3];
                ldsm4(r4, kb_l + off);
                bKl[2*np][0] = r4[0]; bKl[2*np][1] = r4[1];
                bKl[2*np+1][0] = r4[2]; bKl[2*np+1][1] = r4[3];
            }
            #pragma unroll
            for (int nt = 0; nt < 8; nt++) {
                mma16816(S[nt], aQ[g], bKh[nt]);
                mma16816(S[nt], aQ[g], bKl[nt]);
            }
        }

        float tmax0 = -1e30f, tmax1 = -1e30f;
        #pragma unroll
        for (int nt = 0; nt < 8; nt++) {
            int n0 = kk0 + nt * 8 + ncol;
            float km0 = skm[nt * 8 + ncol], km1 = skm[nt * 8 + ncol + 1];
            float s0 = (n0     <= qg0    ) ? S[nt][0] * scale + km0 : -1e30f;
            float s1 = (n0 + 1 <= qg0    ) ? S[nt][1] * scale + km1 : -1e30f;
            float s2 = (n0     <= qg0 + 8) ? S[nt][2] * scale + km0 : -1e30f;
            float s3 = (n0 + 1 <= qg0 + 8) ? S[nt][3] * scale + km1 : -1e30f;
            S[nt][0] = s0; S[nt][1] = s1; S[nt][2] = s2; S[nt][3] = s3;
            tmax0 = fmaxf(tmax0, fmaxf(s0, s1));
            tmax1 = fmaxf(tmax1, fmaxf(s2, s3));
        }
        tmax0 = fmaxf(tmax0, __shfl_xor_sync(0xffffffffu, tmax0, 1));
        tmax0 = fmaxf(tmax0, __shfl_xor_sync(0xffffffffu, tmax0, 2));
        tmax1 = fmaxf(tmax1, __shfl_xor_sync(0xffffffffu, tmax1, 1));
        tmax1 = fmaxf(tmax1, __shfl_xor_sync(0xffffffffu, tmax1, 2));

        float nm0 = fmaxf(m0, tmax0), nm1 = fmaxf(m1, tmax1);
        float cr0 = __expf(m0 - nm0), cr1 = __expf(m1 - nm1);
        m0 = nm0; m1 = nm1;

        float sum0 = 0.f, sum1 = 0.f;
        #pragma unroll
        for (int nt = 0; nt < 8; nt++) {
            float p0 = __expf(S[nt][0] - m0);
            float p1 = __expf(S[nt][1] - m0);
            float p2 = __expf(S[nt][2] - m1);
            float p3 = __expf(S[nt][3] - m1);
            S[nt][0] = p0; S[nt][1] = p1; S[nt][2] = p2; S[nt][3] = p3;
            sum0 += p0 + p1; sum1 += p2 + p3;
        }
        sum0 += __shfl_xor_sync(0xffffffffu, sum0, 1);
        sum0 += __shfl_xor_sync(0xffffffffu, sum0, 2);
        sum1 += __shfl_xor_sync(0xffffffffu, sum1, 1);
        sum1 += __shfl_xor_sync(0xffffffffu, sum1, 2);
        l0 = l0 * cr0 + sum0;
        l1 = l1 * cr1 + sum1;
        #pragma unroll
        for (int nt = 0; nt < 8; nt++) {
            acc[nt][0] *= cr0; acc[nt][1] *= cr0;
            acc[nt][2] *= cr1; acc[nt][3] *= cr1;
        }

        #pragma unroll
        for (int g = 0; g < 4; g++) {
            unsigned aP[4];
            aP[0] = packh2(S[2*g][0],   S[2*g][1]);
            aP[1] = packh2(S[2*g][2],   S[2*g][3]);
            aP[2] = packh2(S[2*g+1][0], S[2*g+1][1]);
            aP[3] = packh2(S[2*g+1][2], S[2*g+1][3]);
            unsigned bVh[8][2], bVl[8][2];
            int brow = g * 16 + (lane & 15);
            #pragma unroll
            for (int np = 0; np < 4; np++) {
                int bcol = np * 16 + ((lane >> 4) << 3);
                unsigned off = (unsigned)(brow * QSTR + bcol) * 2u;
                unsigned r4[4];
                ldsm4t(r4, vb_h + off);
                bVh[2*np][0] = r4[0]; bVh[2*np][1] = r4[1];
                bVh[2*np+1][0] = r4[2]; bVh[2*np+1][1] = r4[3];
                ldsm4t(r4, vb_l + off);
                bVl[2*np][0] = r4[0]; bVl[2*np][1] = r4[1];
                bVl[2*np+1][0] = r4[2]; bVl[2*np+1][1] = r4[3];
            }
            #pragma unroll
            for (int nt = 0; nt < 8; nt++) {
                mma16816(acc[nt], aP, bVh[nt]);
                mma16816(acc[nt], aP, bVl[nt]);
            }
        }
    }

    float il0 = 1.0f / l0, il1 = 1.0f / l1;
    int row0 = q0 + w * 16 + (lane >> 2);
    size_t o0 = ((size_t)(b * Tc + row0)) * Dc + hh * HD + ncol;
    size_t o1 = ((size_t)(b * Tc + row0 + 8)) * Dc + hh * HD + ncol;
    #pragma unroll
    for (int nt = 0; nt < 8; nt++) {
        *(unsigned*)(ctx + o0 + nt*8) = packh2(acc[nt][0] * il0, acc[nt][1] * il0);
        *(unsigned*)(ctx + o1 + nt*8) = packh2(acc[nt][2] * il1, acc[nt][3] * il1);
    }
}

// ---------------- launch -----------------------------------------------------
extern "C" void kernel_launch(void* const* d_in, const int* in_sizes, int n_in,
                              void* d_out, int out_size)
{
    const float* emb    = (const float*)d_in[0];
    const float* amask  = (const float*)d_in[1];
    const float* ln1_w  = (const float*)d_in[2];
    const float* ln1_b  = (const float*)d_in[3];
    const float* attn_w = (const float*)d_in[4];
    const float* attn_b = (const float*)d_in[5];
    const float* proj_w = (const float*)d_in[6];
    const float* proj_b = (const float*)d_in[7];
    const float* ln2_w  = (const float*)d_in[8];
    const float* ln2_b  = (const float*)d_in[9];
    const float* fc_w   = (const float*)d_in[10];
    const float* fc_b   = (const float*)d_in[11];
    const float* fcp_w  = (const float*)d_in[12];
    const float* fcp_b  = (const float*)d_in[13];
    const float* lnf_w  = (const float*)d_in[14];
    const float* lnf_b  = (const float*)d_in[15];
    float* out = (float*)d_out;

    float* h;
    f16 *qhi, *qlo, *x, *ctx, *act;
    f16 *wq_h, *wq_l, *wp_h, *wp_l, *wf_h, *wf_l, *wg_h, *wg_l;
    cudaGetSymbolAddress((void**)&h,    g_h);
    cudaGetSymbolAddress((void**)&qhi,  g_qhi);  cudaGetSymbolAddress((void**)&qlo, g_qlo);
    cudaGetSymbolAddress((void**)&x,    g_x);
    cudaGetSymbolAddress((void**)&ctx,  g_ctx);
    cudaGetSymbolAddress((void**)&act,  g_act);
    cudaGetSymbolAddress((void**)&wq_h, g_wqkv_hi); cudaGetSymbolAddress((void**)&wq_l, g_wqkv_lo);
    cudaGetSymbolAddress((void**)&wp_h, g_wprj_hi); cudaGetSymbolAddress((void**)&wp_l, g_wprj_lo);
    cudaGetSymbolAddress((void**)&wf_h, g_wfc_hi);  cudaGetSymbolAddress((void**)&wf_l, g_wfc_lo);
    cudaGetSymbolAddress((void**)&wg_h, g_wfp_hi);  cudaGetSymbolAddress((void**)&wg_l, g_wfp_lo);

    cudaFuncSetAttribute(gemm2_kernel<1>, cudaFuncAttributeMaxDynamicSharedMemorySize, GSMEM_BYTES);
    cudaFuncSetAttribute(gemm2_kernel<2>, cudaFuncAttributeMaxDynamicSharedMemorySize, GSMEM_BYTES);
    cudaFuncSetAttribute(gemm2_kernel<3>, cudaFuncAttributeMaxDynamicSharedMemorySize, GSMEM_BYTES);
    cudaFuncSetAttribute(attn_mma_kernel, cudaFuncAttributeMaxDynamicSharedMemorySize, ASMEM_BYTES);

    // weight splits [K,N] hi/lo (fp16)
    { int n4 = Lc*Dc*3*Dc/4; split4_kernel<<<(n4+255)/256, 256>>>(attn_w, wq_h, wq_l, n4); }
    { int n4 = Lc*Dc*Dc/4;   split4_kernel<<<(n4+255)/256, 256>>>(proj_w, wp_h, wp_l, n4); }
    { int n4 = Lc*Dc*Ic/4;   split4_kernel<<<(n4+255)/256, 256>>>(fc_w,   wf_h, wf_l, n4); }
    { int n4 = Lc*Ic*Dc/4;   split4_kernel<<<(n4+255)/256, 256>>>(fcp_w,  wg_h, wg_l, n4); }

    for (int l = 0; l < Lc; l++) {
        const float* hin = (l == 0) ? emb : h;   // layer-0 reads embeds directly
        // x = ln1(hin) -> fp16
        ln_kernel<true><<<ROWS, 256>>>(hin, ln1_w + (size_t)l*Dc, ln1_b + (size_t)l*Dc,
                                       nullptr, x);
        // qkv = x @ attn_w + attn_b  -> fp16 hi/lo
        gemm2_kernel<3><<<dim3(3*Dc/GBN, ROWS/GBM), 256, GSMEM_BYTES>>>(
            x, wq_h + (size_t)l*Dc*3*Dc, wq_l + (size_t)l*Dc*3*Dc,
            attn_b + (size_t)l*3*Dc, nullptr, nullptr, qhi, qlo,
            ROWS, 3*Dc, Dc);
        // ctx = attention(qkv) -> fp16
        attn_mma_kernel<<<dim3(Tc/AQ, Bc*Hc), 256, ASMEM_BYTES>>>(qhi, qlo, amask, ctx);
        // h = hin + ctx @ proj_w + proj_b
        gemm2_kernel<1><<<dim3(Dc/GBN, ROWS/GBM), 256, GSMEM_BYTES>>>(
            ctx, wp_h + (size_t)l*Dc*Dc, wp_l + (size_t)l*Dc*Dc,
            proj_b + (size_t)l*Dc, hin, h, nullptr, nullptr,
            ROWS, Dc, Dc);
        // x = ln2(h) -> fp16
        ln_kernel<true><<<ROWS, 256>>>(h, ln2_w + (size_t)l*Dc, ln2_b + (size_t)l*Dc,
                                       nullptr, x);
        // act = relu(x @ fc_w + fc_b) -> fp16
        gemm2_kernel<2><<<dim3(Ic/GBN, ROWS/GBM), 256, GSMEM_BYTES>>>(
            x, wf_h + (size_t)l*Dc*Ic, wf_l + (size_t)l*Dc*Ic,
            fc_b + (size_t)l*Ic, nullptr, nullptr, act, nullptr,
            ROWS, Ic, Dc);
        // h = h + act @ fcp_w + fcp_b
        gemm2_kernel<1><<<dim3(Dc/GBN, ROWS/GBM), 256, GSMEM_BYTES>>>(
            act, wg_h + (size_t)l*Ic*Dc, wg_l + (size_t)l*Ic*Dc,
            fcp_b + (size_t)l*Dc, h, h, nullptr, nullptr,
            ROWS, Dc, Ic);
    }
    // out = ln_f(h) (fp32)
    ln_kernel<false><<<ROWS, 256>>>(h, lnf_w, lnf_b, out, nullptr);
}